// round 16
// baseline (speedup 1.0000x reference)
#include <cuda_runtime.h>
#include <cstdint>

// Problem constants (fixed shapes per reference)
#define NMAX   100000
#define EMAX   1600000
#define INF_   64          // in feats
#define OH     256         // OUT*H
#define NHEAD  4
#define SLOPE  0.2f

// ---------------- device scratch (static: allocation-free) ----------------
__device__ float d_Z[(size_t)NMAX * OH];          // projected features  [N,256]
__device__ float d_el[(size_t)NMAX * NHEAD];      // e_l  [N,4]
__device__ float d_er[(size_t)NMAX * NHEAD];      // e_r  [N,4]
__device__ int   d_deg[NMAX];
__device__ int   d_start[NMAX];
__device__ int   d_pos[NMAX];
__device__ int   d_cols[EMAX];                    // col indices grouped by row

// ---------------- K0: zero degree array ----------------
__global__ void zero_deg_k(int n) {
    int i = blockIdx.x * blockDim.x + threadIdx.x;
    if (i < n) d_deg[i] = 0;
}

// ---------------- K1: degree histogram over row[] ----------------
__global__ void hist_k(const int* __restrict__ row, int E) {
    int e = blockIdx.x * blockDim.x + threadIdx.x;
    if (e < E) atomicAdd(&d_deg[row[e]], 1);
}

// ---------------- K2: single-block exclusive scan -> start, pos ----------------
__global__ void scan_k(int n) {
    __shared__ int s[1024];
    int t = threadIdx.x;
    int chunk = (n + 1023) / 1024;
    int b = t * chunk;
    int e = min(b + chunk, n);
    int sum = 0;
    for (int i = b; i < e; i++) sum += d_deg[i];
    s[t] = sum;
    __syncthreads();
    // Hillis-Steele inclusive scan
    for (int off = 1; off < 1024; off <<= 1) {
        int v = (t >= off) ? s[t - off] : 0;
        __syncthreads();
        s[t] += v;
        __syncthreads();
    }
    int run = (t > 0) ? s[t - 1] : 0;
    for (int i = b; i < e; i++) {
        d_start[i] = run;
        d_pos[i]   = run;
        run += d_deg[i];
    }
}

// ---------------- K3: scatter edges into CSR (grouped by row) ----------------
__global__ void scatter_k(const int* __restrict__ row, const int* __restrict__ col, int E) {
    int e = blockIdx.x * blockDim.x + threadIdx.x;
    if (e < E) {
        int p = atomicAdd(&d_pos[row[e]], 1);
        d_cols[p] = col[e];
    }
}

// ---------------- K4: GEMM  Z = feat @ W^T + bias ----------------
// feat [N,64], W [256,64], Z [N,256]. Block: 32 rows x 128 cols. grid (N/32, 2).
__global__ __launch_bounds__(256) void gemm_k(const float* __restrict__ feat,
                                              const float* __restrict__ W,
                                              const float* __restrict__ bias,
                                              int n) {
    __shared__ __align__(16) float sF[32][INF_];      // broadcast reads
    __shared__ __align__(16) float sW[128][68];       // stride 68 -> conflict-free f4

    int t = threadIdx.x;                 // 0..255
    int rowBase = blockIdx.x * 32;
    int by = blockIdx.y;                 // column half: 0 or 1

    // stage W tile [128 rows of W starting at by*128] -> sW (float4)
    const float4* Wv = (const float4*)(W + (size_t)by * 128 * INF_);
    #pragma unroll
    for (int idx = t; idx < 128 * 16; idx += 256) {
        int j  = idx >> 4;
        int k4 = idx & 15;
        float4 v = Wv[idx];
        *(float4*)&sW[j][k4 * 4] = v;
    }
    // stage feat tile [32 x 64]
    const float4* Fv = (const float4*)(feat + (size_t)rowBase * INF_);
    #pragma unroll
    for (int idx = t; idx < 512; idx += 256) {
        int r = idx >> 4;
        float4 v = make_float4(0.f, 0.f, 0.f, 0.f);
        if (rowBase + r < n) v = Fv[idx];
        int k4 = idx & 15;
        *(float4*)&sF[r][k4 * 4] = v;
    }
    __syncthreads();

    int jj = t & 127;
    int r0 = (t >> 7) << 4;              // 0 or 16
    float acc[16];
    #pragma unroll
    for (int r = 0; r < 16; r++) acc[r] = 0.f;

    #pragma unroll
    for (int k4 = 0; k4 < 16; k4++) {
        float4 wv = *(float4*)&sW[jj][k4 * 4];
        #pragma unroll
        for (int r = 0; r < 16; r++) {
            float4 fv = *(float4*)&sF[r0 + r][k4 * 4];
            acc[r] = fmaf(wv.x, fv.x, acc[r]);
            acc[r] = fmaf(wv.y, fv.y, acc[r]);
            acc[r] = fmaf(wv.z, fv.z, acc[r]);
            acc[r] = fmaf(wv.w, fv.w, acc[r]);
        }
    }

    int jglob = by * 128 + jj;
    float b = bias[jglob];
    #pragma unroll
    for (int r = 0; r < 16; r++) {
        int rowg = rowBase + r0 + r;
        if (rowg < n) d_Z[(size_t)rowg * OH + jglob] = acc[r] + b;
    }
}

// ---------------- K5: per-node attention logits e_l, e_r ----------------
// e_l[n,h] = sum_{t: t%4==h} Z[n,t]*a_l[t]   (a_l flat layout (OUT,H) == Z column layout)
__global__ __launch_bounds__(256) void eler_k(const float* __restrict__ al,
                                              const float* __restrict__ ar,
                                              int n) {
    int i = blockIdx.x;
    int t = threadIdx.x;
    float z = d_Z[(size_t)i * OH + t];
    float pl = z * al[t];
    float pr = z * ar[t];
    // butterfly over lanes with same (lane & 3)
    #pragma unroll
    for (int off = 4; off < 32; off <<= 1) {
        pl += __shfl_xor_sync(0xffffffffu, pl, off);
        pr += __shfl_xor_sync(0xffffffffu, pr, off);
    }
    __shared__ float spl[8][4], spr[8][4];
    int w = t >> 5, l = t & 31;
    if (l < 4) { spl[w][l] = pl; spr[w][l] = pr; }
    __syncthreads();
    if (t < 4) {
        float a = 0.f, b = 0.f;
        #pragma unroll
        for (int ww = 0; ww < 8; ww++) { a += spl[ww][t]; b += spr[ww][t]; }
        d_el[i * 4 + t] = a;
        d_er[i * 4 + t] = b;
    }
}

// ---------------- K6: segment softmax + weighted aggregation ----------------
// one block (256 threads) per destination node. thread t owns output column t (h = t&3).
__global__ __launch_bounds__(256) void aggregate_k(float* __restrict__ out, int n) {
    int i = blockIdx.x;
    int t = threadIdx.x;
    int d  = d_deg[i];
    if (d == 0) {                              // no incoming edges -> zeros
        out[(size_t)i * OH + t] = 0.f;
        return;
    }
    int s0 = d_start[i];

    __shared__ float s_m[4];
    __shared__ float s_sum[4];
    __shared__ float s_w[64 * 4];
    __shared__ int   s_c[64];

    float4 el4 = *(const float4*)&d_el[i * 4];

    // phase 1: per-head max of leaky(e) over incident edges (warp 0)
    if (t < 32) {
        float m0 = -1e30f, m1 = -1e30f, m2 = -1e30f, m3 = -1e30f;
        for (int e = t; e < d; e += 32) {
            int c = d_cols[s0 + e];
            float4 er4 = *(const float4*)&d_er[c * 4];
            float a0 = el4.x + er4.x; a0 = a0 > 0.f ? a0 : SLOPE * a0;
            float a1 = el4.y + er4.y; a1 = a1 > 0.f ? a1 : SLOPE * a1;
            float a2 = el4.z + er4.z; a2 = a2 > 0.f ? a2 : SLOPE * a2;
            float a3 = el4.w + er4.w; a3 = a3 > 0.f ? a3 : SLOPE * a3;
            m0 = fmaxf(m0, a0); m1 = fmaxf(m1, a1);
            m2 = fmaxf(m2, a2); m3 = fmaxf(m3, a3);
        }
        #pragma unroll
        for (int off = 16; off > 0; off >>= 1) {
            m0 = fmaxf(m0, __shfl_xor_sync(0xffffffffu, m0, off));
            m1 = fmaxf(m1, __shfl_xor_sync(0xffffffffu, m1, off));
            m2 = fmaxf(m2, __shfl_xor_sync(0xffffffffu, m2, off));
            m3 = fmaxf(m3, __shfl_xor_sync(0xffffffffu, m3, off));
        }
        if (t == 0) { s_m[0] = m0; s_m[1] = m1; s_m[2] = m2; s_m[3] = m3; }
    }
    if (t < 4) s_sum[t] = 0.f;
    __syncthreads();

    int   h   = t & 3;
    float acc = 0.f;
    float ls0 = 0.f, ls1 = 0.f, ls2 = 0.f, ls3 = 0.f;

    for (int base = 0; base < d; base += 64) {
        if (t < 64) {
            int k = base + t;
            if (k < d) {
                int c = d_cols[s0 + k];
                float4 er4 = *(const float4*)&d_er[c * 4];
                float a0 = el4.x + er4.x; a0 = a0 > 0.f ? a0 : SLOPE * a0;
                float a1 = el4.y + er4.y; a1 = a1 > 0.f ? a1 : SLOPE * a1;
                float a2 = el4.z + er4.z; a2 = a2 > 0.f ? a2 : SLOPE * a2;
                float a3 = el4.w + er4.w; a3 = a3 > 0.f ? a3 : SLOPE * a3;
                float w0 = __expf(a0 - s_m[0]);
                float w1 = __expf(a1 - s_m[1]);
                float w2 = __expf(a2 - s_m[2]);
                float w3 = __expf(a3 - s_m[3]);
                s_w[t * 4 + 0] = w0; s_w[t * 4 + 1] = w1;
                s_w[t * 4 + 2] = w2; s_w[t * 4 + 3] = w3;
                s_c[t] = c;
                ls0 += w0; ls1 += w1; ls2 += w2; ls3 += w3;
            }
        }
        __syncthreads();
        int lim = min(64, d - base);
        const float* __restrict__ Zb = d_Z;
        #pragma unroll 4
        for (int k2 = 0; k2 < lim; k2++) {
            acc = fmaf(s_w[k2 * 4 + h], __ldg(&Zb[(size_t)s_c[k2] * OH + t]), acc);
        }
        __syncthreads();
    }

    if (t < 64) {
        atomicAdd(&s_sum[0], ls0);
        atomicAdd(&s_sum[1], ls1);
        atomicAdd(&s_sum[2], ls2);
        atomicAdd(&s_sum[3], ls3);
    }
    __syncthreads();

    out[(size_t)i * OH + t] = acc / s_sum[h];
}

// ---------------- launcher ----------------
extern "C" void kernel_launch(void* const* d_in, const int* in_sizes, int n_in,
                              void* d_out, int out_size) {
    const float* feat = (const float*)d_in[0];   // [N,64]
    const float* Ww   = (const float*)d_in[1];   // [256,64]
    const float* Wb   = (const float*)d_in[2];   // [256]
    const float* a_l  = (const float*)d_in[3];   // [1,64,4] flat 256
    const float* a_r  = (const float*)d_in[4];   // [1,64,4] flat 256
    const int*   row  = (const int*)d_in[5];     // [E]
    const int*   col  = (const int*)d_in[6];     // [E]
    float* out = (float*)d_out;

    int n = in_sizes[0] / INF_;
    int E = in_sizes[5];

    // CSR build
    zero_deg_k<<<(n + 255) / 256, 256>>>(n);
    hist_k<<<(E + 255) / 256, 256>>>(row, E);
    scan_k<<<1, 1024>>>(n);
    scatter_k<<<(E + 255) / 256, 256>>>(row, col, E);

    // projection + logits
    dim3 ggrid((n + 31) / 32, 2);
    gemm_k<<<ggrid, 256>>>(feat, Ww, Wb, n);
    eler_k<<<n, 256>>>(a_l, a_r, n);

    // softmax + aggregation
    aggregate_k<<<n, 256>>>(out, n);
}